// round 1
// baseline (speedup 1.0000x reference)
#include <cuda_runtime.h>
#include <cstdint>

// ---------------- problem constants ----------------
#define Nn     30000
#define F_IN   128
#define F_H    256
#define NHEAD  8
#define CCH    32
#define E_BASE 480000
#define E_TOT  (E_BASE + Nn)     // with self loops
#define NEG_SLOPE 0.2f

// ---------------- device scratch (no allocs allowed) ----------------
__device__ float    g_h  [(size_t)Nn * F_H];   // per-layer node features h = x@W
__device__ float    g_agg[(size_t)Nn * F_H];   // aggregation accumulator
__device__ float    g_x2 [(size_t)Nn * F_H];   // layer-1 output (elu)
__device__ float    g_as [(size_t)Nn * NHEAD];
__device__ float    g_ad [(size_t)Nn * NHEAD];
__device__ unsigned g_max[(size_t)Nn * NHEAD]; // ordered-uint encoded float max
__device__ float    g_den[(size_t)Nn * NHEAD];
__device__ float    g_ev [(size_t)E_TOT * NHEAD]; // per-edge-head scratch (e then w)

// ordered-float <-> uint monotone encoding for atomicMax
__device__ __forceinline__ unsigned f2o(float f) {
    unsigned u = __float_as_uint(f);
    return (u & 0x80000000u) ? ~u : (u | 0x80000000u);
}
__device__ __forceinline__ float o2f(unsigned u) {
    u = (u & 0x80000000u) ? (u & 0x7FFFFFFFu) : ~u;
    return __uint_as_float(u);
}

// ---------------- SGEMM: C[nrows,256] = A[nrows,K] @ W[K,256] ----------------
// 64x64 tile, BK=16, 256 threads, 4x4 micro-tile per thread.
template <int K>
__global__ void k_gemm(const float* __restrict__ A, const float* __restrict__ W,
                       float* __restrict__ Cout) {
    __shared__ float As[16][64];
    __shared__ float Bs[16][68];   // 68 floats = 272B row pitch (16B aligned)

    const int tid = threadIdx.x;
    const int tx = tid & 15, ty = tid >> 4;
    const int row0 = blockIdx.y * 64;
    const int col0 = blockIdx.x * 64;

    float acc[4][4];
#pragma unroll
    for (int i = 0; i < 4; i++)
#pragma unroll
        for (int j = 0; j < 4; j++) acc[i][j] = 0.f;

    const int ar = tid >> 2;            // 0..63
    const int ac = (tid & 3) * 4;       // 0,4,8,12
    const int br = tid >> 4;            // 0..15
    const int bc = (tid & 15) * 4;      // 0..60

    for (int k0 = 0; k0 < K; k0 += 16) {
        float4 av = make_float4(0.f, 0.f, 0.f, 0.f);
        if (row0 + ar < Nn)
            av = *(const float4*)(A + (size_t)(row0 + ar) * K + k0 + ac);
        As[ac + 0][ar] = av.x; As[ac + 1][ar] = av.y;
        As[ac + 2][ar] = av.z; As[ac + 3][ar] = av.w;

        float4 bv = *(const float4*)(W + (size_t)(k0 + br) * F_H + col0 + bc);
        *(float4*)&Bs[br][bc] = bv;
        __syncthreads();

#pragma unroll
        for (int k = 0; k < 16; k++) {
            float a0 = As[k][ty * 4 + 0], a1 = As[k][ty * 4 + 1];
            float a2 = As[k][ty * 4 + 2], a3 = As[k][ty * 4 + 3];
            float b0 = Bs[k][tx * 4 + 0], b1 = Bs[k][tx * 4 + 1];
            float b2 = Bs[k][tx * 4 + 2], b3 = Bs[k][tx * 4 + 3];
            acc[0][0] += a0 * b0; acc[0][1] += a0 * b1; acc[0][2] += a0 * b2; acc[0][3] += a0 * b3;
            acc[1][0] += a1 * b0; acc[1][1] += a1 * b1; acc[1][2] += a1 * b2; acc[1][3] += a1 * b3;
            acc[2][0] += a2 * b0; acc[2][1] += a2 * b1; acc[2][2] += a2 * b2; acc[2][3] += a2 * b3;
            acc[3][0] += a3 * b0; acc[3][1] += a3 * b1; acc[3][2] += a3 * b2; acc[3][3] += a3 * b3;
        }
        __syncthreads();
    }

#pragma unroll
    for (int i = 0; i < 4; i++) {
        int r = row0 + ty * 4 + i;
        if (r < Nn) {
            float4 v = make_float4(acc[i][0], acc[i][1], acc[i][2], acc[i][3]);
            *(float4*)(Cout + (size_t)r * F_H + col0 + tx * 4) = v;
        }
    }
}

// ---------------- alpha projections: as/ad[n,h] = <h[n,h,:], a_src/dst[h,:]> --------
__global__ void k_alpha(const float* __restrict__ a_src, const float* __restrict__ a_dst) {
    int idx = blockIdx.x * blockDim.x + threadIdx.x;
    if (idx >= Nn * NHEAD) return;
    int n = idx >> 3, h = idx & 7;
    const float4* hp = (const float4*)(g_h + (size_t)n * F_H + h * CCH);
    const float4* as = (const float4*)(a_src + h * CCH);
    const float4* ad = (const float4*)(a_dst + h * CCH);
    float s = 0.f, d = 0.f;
#pragma unroll
    for (int i = 0; i < 8; i++) {
        float4 v = hp[i], a = as[i], b = ad[i];
        s += v.x * a.x + v.y * a.y + v.z * a.z + v.w * a.w;
        d += v.x * b.x + v.y * b.y + v.z * b.z + v.w * b.w;
    }
    g_as[idx] = s;
    g_ad[idx] = d;
}

// ---------------- init accumulators ----------------
__global__ void k_init() {
    const unsigned NEG_INF_ENC = f2o(-__int_as_float(0x7F800000)); // enc(-inf)
    for (int i = blockIdx.x * blockDim.x + threadIdx.x; i < Nn * F_H;
         i += gridDim.x * blockDim.x) {
        g_agg[i] = 0.f;
        if (i < Nn * NHEAD) { g_den[i] = 0.f; g_max[i] = NEG_INF_ENC; }
    }
}

// ---------------- edge pass 1: e = leaky(as[src]+ad[dst]); segment max -----------
__global__ void k_edge_max(const int* __restrict__ ei, int E) {
    int e = blockIdx.x * blockDim.x + threadIdx.x;
    int etot = E + Nn;
    if (e >= etot) return;
    int src = (e < E) ? ei[e] : (e - E);
    int dst = (e < E) ? ei[E + e] : (e - E);
#pragma unroll
    for (int h = 0; h < NHEAD; h++) {
        float v = g_as[src * NHEAD + h] + g_ad[dst * NHEAD + h];
        v = (v > 0.f) ? v : NEG_SLOPE * v;
        g_ev[(size_t)e * NHEAD + h] = v;
        atomicMax(&g_max[dst * NHEAD + h], f2o(v));
    }
}

// ---------------- edge pass 2: w = exp(e - max[dst]); segment sum ---------------
__global__ void k_edge_exp(const int* __restrict__ ei, int E) {
    int e = blockIdx.x * blockDim.x + threadIdx.x;
    int etot = E + Nn;
    if (e >= etot) return;
    int dst = (e < E) ? ei[E + e] : (e - E);
#pragma unroll
    for (int h = 0; h < NHEAD; h++) {
        float m = o2f(g_max[dst * NHEAD + h]);
        float w = __expf(g_ev[(size_t)e * NHEAD + h] - m);
        g_ev[(size_t)e * NHEAD + h] = w;
        atomicAdd(&g_den[dst * NHEAD + h], w);
    }
}

// ---------------- edge pass 3: agg[dst] += h[src] * alpha  (vec4 RED) -----------
__global__ void k_aggregate(const int* __restrict__ ei, int E) {
    int idx = blockIdx.x * blockDim.x + threadIdx.x;   // (edge, head)
    int etot = E + Nn;
    if (idx >= etot * NHEAD) return;
    int e = idx >> 3, h = idx & 7;
    int src = (e < E) ? ei[e] : (e - E);
    int dst = (e < E) ? ei[E + e] : (e - E);
    float alpha = g_ev[idx] / (g_den[dst * NHEAD + h] + 1e-16f);
    const float4* hp = (const float4*)(g_h + (size_t)src * F_H + h * CCH);
    float* op = g_agg + (size_t)dst * F_H + h * CCH;
#pragma unroll
    for (int i = 0; i < 8; i++) {
        float4 v = hp[i];
        asm volatile("red.global.add.v4.f32 [%0], {%1,%2,%3,%4};"
                     :: "l"(op + i * 4),
                        "f"(v.x * alpha), "f"(v.y * alpha),
                        "f"(v.z * alpha), "f"(v.w * alpha)
                     : "memory");
    }
}

// ---------------- epilogue layer 1: x2 = elu(agg + b) ----------------
__global__ void k_elu1(const float* __restrict__ b) {
    int idx = blockIdx.x * blockDim.x + threadIdx.x;
    if (idx >= Nn * F_H) return;
    float v = g_agg[idx] + b[idx & (F_H - 1)];
    g_x2[idx] = (v > 0.f) ? v : expm1f(v);
}

// ---------------- epilogue layer 2: out[n] = elu(agg+b2) . Wl + bl --------------
__global__ void k_final(const float* __restrict__ b2, const float* __restrict__ Wl,
                        const float* __restrict__ bl, float* __restrict__ out) {
    int gid = blockIdx.x * blockDim.x + threadIdx.x;
    int warp = gid >> 5, lane = gid & 31;
    if (warp >= Nn) return;
    float s = 0.f;
#pragma unroll
    for (int i = lane; i < F_H; i += 32) {
        float v = g_agg[(size_t)warp * F_H + i] + b2[i];
        v = (v > 0.f) ? v : expm1f(v);
        s += v * Wl[i];
    }
#pragma unroll
    for (int o = 16; o > 0; o >>= 1) s += __shfl_down_sync(0xFFFFFFFFu, s, o);
    if (lane == 0) out[warp] = s + bl[0];
}

// ---------------- host ----------------
extern "C" void kernel_launch(void* const* d_in, const int* in_sizes, int n_in,
                              void* d_out, int out_size) {
    const float* x    = (const float*)d_in[0];
    const int*   ei   = (const int*)  d_in[1];
    const float* W1   = (const float*)d_in[2];
    const float* a1s  = (const float*)d_in[3];
    const float* a1d  = (const float*)d_in[4];
    const float* b1   = (const float*)d_in[5];
    const float* W2   = (const float*)d_in[6];
    const float* a2s  = (const float*)d_in[7];
    const float* a2d  = (const float*)d_in[8];
    const float* b2   = (const float*)d_in[9];
    const float* Wl   = (const float*)d_in[10];
    const float* bl   = (const float*)d_in[11];
    float* out = (float*)d_out;

    const int E = in_sizes[1] / 2;          // 480000
    const int etot = E + Nn;                // 510000

    float* g_h_p;   cudaGetSymbolAddress((void**)&g_h_p,  g_h);
    float* g_x2_p;  cudaGetSymbolAddress((void**)&g_x2_p, g_x2);

    dim3 gemm_grid(F_H / 64, (Nn + 63) / 64);
    const int T = 256;
    int nh_blocks   = (Nn * NHEAD + T - 1) / T;
    int e_blocks    = (etot + T - 1) / T;
    int eh_blocks   = ((size_t)etot * NHEAD + T - 1) / T;
    int nf_blocks   = (Nn * F_H + T - 1) / T;
    int init_blocks = 1024;
    int fin_blocks  = (Nn * 32 + T - 1) / T;

    // ---------- layer 1 ----------
    k_gemm<F_IN><<<gemm_grid, T>>>(x, W1, g_h_p);
    k_alpha<<<nh_blocks, T>>>(a1s, a1d);
    k_init<<<init_blocks, T>>>();
    k_edge_max<<<e_blocks, T>>>(ei, E);
    k_edge_exp<<<e_blocks, T>>>(ei, E);
    k_aggregate<<<eh_blocks, T>>>(ei, E);
    k_elu1<<<nf_blocks, T>>>(b1);

    // ---------- layer 2 ----------
    k_gemm<F_H><<<gemm_grid, T>>>(g_x2_p, W2, g_h_p);
    k_alpha<<<nh_blocks, T>>>(a2s, a2d);
    k_init<<<init_blocks, T>>>();
    k_edge_max<<<e_blocks, T>>>(ei, E);
    k_edge_exp<<<e_blocks, T>>>(ei, E);
    k_aggregate<<<eh_blocks, T>>>(ei, E);
    k_final<<<fin_blocks, T>>>(b2, Wl, bl, out);
}

// round 2
// speedup vs baseline: 2.0571x; 2.0571x over previous
#include <cuda_runtime.h>
#include <cstdint>

// ---------------- problem constants ----------------
#define Nn     30000
#define F_IN   128
#define F_H    256
#define NHEAD  8
#define CCH    32
#define NEG_SLOPE 0.2f

// ---------------- device scratch (no allocs allowed) ----------------
__device__ float g_h   [(size_t)Nn * F_H];   // node features h = x@W (per layer)
__device__ float g_agg [(size_t)Nn * F_H];   // unnormalized aggregation
__device__ float g_x2  [(size_t)Nn * F_H];   // layer-1 output (elu)
__device__ float g_as  [(size_t)Nn * NHEAD];
__device__ float g_ad  [(size_t)Nn * NHEAD];
__device__ float g_den1[(size_t)Nn * NHEAD];
__device__ float g_den2[(size_t)Nn * NHEAD];

__device__ __forceinline__ void red4(float* p, float a, float b, float c, float d) {
    asm volatile("red.global.add.v4.f32 [%0], {%1,%2,%3,%4};"
                 :: "l"(p), "f"(a), "f"(b), "f"(c), "f"(d) : "memory");
}

__device__ __forceinline__ float leaky(float v) {
    return (v > 0.f) ? v : NEG_SLOPE * v;
}

// ---------------- SGEMM: C[Nn,256] = A[Nn,K] @ W[K,256] ----------------
// 128x128 tile, BK=8, 256 threads, 8x8 micro-tile.
template <int K>
__global__ void __launch_bounds__(256) k_gemm(const float* __restrict__ A,
                                              const float* __restrict__ W,
                                              float* __restrict__ Cout) {
    __shared__ float As[8][128];
    __shared__ float Bs[8][128];

    const int tid  = threadIdx.x;
    const int tx   = tid & 15, ty = tid >> 4;
    const int row0 = blockIdx.y * 128;
    const int col0 = blockIdx.x * 128;

    float acc[8][8];
#pragma unroll
    for (int i = 0; i < 8; i++)
#pragma unroll
        for (int j = 0; j < 8; j++) acc[i][j] = 0.f;

    const int ar = tid >> 1;            // 0..127
    const int ac = (tid & 1) * 4;       // 0 or 4
    const int br = tid >> 5;            // 0..7
    const int bc = (tid & 31) * 4;      // 0..124

    for (int k0 = 0; k0 < K; k0 += 8) {
        float4 av = make_float4(0.f, 0.f, 0.f, 0.f);
        if (row0 + ar < Nn)
            av = *(const float4*)(A + (size_t)(row0 + ar) * K + k0 + ac);
        As[ac + 0][ar] = av.x; As[ac + 1][ar] = av.y;
        As[ac + 2][ar] = av.z; As[ac + 3][ar] = av.w;

        *(float4*)&Bs[br][bc] =
            *(const float4*)(W + (size_t)(k0 + br) * F_H + col0 + bc);
        __syncthreads();

#pragma unroll
        for (int k = 0; k < 8; k++) {
            float a[8], b[8];
            *(float4*)&a[0] = *(const float4*)&As[k][ty * 8 + 0];
            *(float4*)&a[4] = *(const float4*)&As[k][ty * 8 + 4];
            *(float4*)&b[0] = *(const float4*)&Bs[k][tx * 8 + 0];
            *(float4*)&b[4] = *(const float4*)&Bs[k][tx * 8 + 4];
#pragma unroll
            for (int i = 0; i < 8; i++)
#pragma unroll
                for (int j = 0; j < 8; j++) acc[i][j] += a[i] * b[j];
        }
        __syncthreads();
    }

#pragma unroll
    for (int i = 0; i < 8; i++) {
        int r = row0 + ty * 8 + i;
        if (r < Nn) {
            *(float4*)(Cout + (size_t)r * F_H + col0 + tx * 8 + 0) =
                make_float4(acc[i][0], acc[i][1], acc[i][2], acc[i][3]);
            *(float4*)(Cout + (size_t)r * F_H + col0 + tx * 8 + 4) =
                make_float4(acc[i][4], acc[i][5], acc[i][6], acc[i][7]);
        }
    }
}

// ---------------- alpha projections ----------------
__global__ void k_alpha(const float* __restrict__ a_src, const float* __restrict__ a_dst) {
    int idx = blockIdx.x * blockDim.x + threadIdx.x;
    if (idx >= Nn * NHEAD) return;
    int n = idx >> 3, h = idx & 7;
    const float4* hp = (const float4*)(g_h + (size_t)n * F_H + h * CCH);
    const float4* as = (const float4*)(a_src + h * CCH);
    const float4* ad = (const float4*)(a_dst + h * CCH);
    float s = 0.f, d = 0.f;
#pragma unroll
    for (int i = 0; i < 8; i++) {
        float4 v = hp[i], a = as[i], b = ad[i];
        s += v.x * a.x + v.y * a.y + v.z * a.z + v.w * a.w;
        d += v.x * b.x + v.y * b.y + v.z * b.z + v.w * b.w;
    }
    g_as[idx] = s;
    g_ad[idx] = d;
}

// ---------------- init accumulators (once per call) ----------------
__global__ void k_init() {
    for (int i = blockIdx.x * blockDim.x + threadIdx.x; i < Nn * F_H;
         i += gridDim.x * blockDim.x) {
        g_agg[i] = 0.f;
        if (i < Nn * NHEAD) { g_den1[i] = 0.f; g_den2[i] = 0.f; }
    }
}

// ---------------- fused edge pass: den += exp(e), agg += exp(e)*h[src] ----------
// 8 threads per edge; thread j owns float4 lanes j*4 + i*32 (i = head index).
__global__ void k_edge(const int* __restrict__ ei, int E, float* __restrict__ den) {
    int idx = blockIdx.x * blockDim.x + threadIdx.x;
    if (idx >= E * NHEAD) return;
    int e = idx >> 3, j = idx & 7;
    int src = __ldg(&ei[e]);
    int dst = __ldg(&ei[E + e]);

    // all 8 head weights (recomputed per thread; MUFU is cheap vs LTS)
    float4 s0 = *(const float4*)(g_as + src * NHEAD);
    float4 s1 = *(const float4*)(g_as + src * NHEAD + 4);
    float4 d0 = *(const float4*)(g_ad + dst * NHEAD);
    float4 d1 = *(const float4*)(g_ad + dst * NHEAD + 4);
    float w[8];
    w[0] = __expf(leaky(s0.x + d0.x)); w[1] = __expf(leaky(s0.y + d0.y));
    w[2] = __expf(leaky(s0.z + d0.z)); w[3] = __expf(leaky(s0.w + d0.w));
    w[4] = __expf(leaky(s1.x + d1.x)); w[5] = __expf(leaky(s1.y + d1.y));
    w[6] = __expf(leaky(s1.z + d1.z)); w[7] = __expf(leaky(s1.w + d1.w));

    atomicAdd(&den[dst * NHEAD + j], w[j]);   // one denom lane per thread

    const float* hp = g_h + (size_t)src * F_H + j * 4;
    float* op = g_agg + (size_t)dst * F_H + j * 4;
#pragma unroll
    for (int i = 0; i < 8; i++) {             // i = head; 128B-contiguous per warp-instr
        float4 v = *(const float4*)(hp + i * 32);
        red4(op + i * 32, v.x * w[i], v.y * w[i], v.z * w[i], v.w * w[i]);
    }
}

// ---------------- epilogue layer 1: x2 = elu((agg + w_self*h)/(den + w_self) + b)
// Also zeroes g_agg (per-element, safe) for layer 2.
__global__ void k_elu1(const float* __restrict__ b) {
    int idx = blockIdx.x * blockDim.x + threadIdx.x;
    if (idx >= Nn * F_H) return;
    int n = idx >> 8, f = idx & 255, h = f >> 5;
    float ws = __expf(leaky(g_as[n * NHEAD + h] + g_ad[n * NHEAD + h]));
    float num = g_agg[idx] + ws * g_h[idx];
    float den = g_den1[n * NHEAD + h] + ws;
    float v = num / den + b[f];
    g_x2[idx] = (v > 0.f) ? v : expm1f(v);
    g_agg[idx] = 0.f;
}

// ---------------- epilogue layer 2 + linear head ----------------
__global__ void k_final(const float* __restrict__ b2, const float* __restrict__ Wl,
                        const float* __restrict__ bl, float* __restrict__ out) {
    int gid = blockIdx.x * blockDim.x + threadIdx.x;
    int n = gid >> 5, lane = gid & 31;
    if (n >= Nn) return;
    float s = 0.f;
#pragma unroll
    for (int k = 0; k < 8; k++) {             // f = lane + 32k, head = k
        int f = lane + 32 * k;
        float ws = __expf(leaky(g_as[n * NHEAD + k] + g_ad[n * NHEAD + k]));
        float num = g_agg[(size_t)n * F_H + f] + ws * g_h[(size_t)n * F_H + f];
        float den = g_den2[n * NHEAD + k] + ws;
        float v = num / den + b2[f];
        v = (v > 0.f) ? v : expm1f(v);
        s += v * Wl[f];
    }
#pragma unroll
    for (int o = 16; o > 0; o >>= 1) s += __shfl_down_sync(0xFFFFFFFFu, s, o);
    if (lane == 0) out[n] = s + bl[0];
}

// ---------------- host ----------------
extern "C" void kernel_launch(void* const* d_in, const int* in_sizes, int n_in,
                              void* d_out, int out_size) {
    const float* x   = (const float*)d_in[0];
    const int*   ei  = (const int*)  d_in[1];
    const float* W1  = (const float*)d_in[2];
    const float* a1s = (const float*)d_in[3];
    const float* a1d = (const float*)d_in[4];
    const float* b1  = (const float*)d_in[5];
    const float* W2  = (const float*)d_in[6];
    const float* a2s = (const float*)d_in[7];
    const float* a2d = (const float*)d_in[8];
    const float* b2  = (const float*)d_in[9];
    const float* Wl  = (const float*)d_in[10];
    const float* bl  = (const float*)d_in[11];
    float* out = (float*)d_out;

    const int E = in_sizes[1] / 2;          // 480000

    float* g_h_p;    cudaGetSymbolAddress((void**)&g_h_p,    g_h);
    float* g_x2_p;   cudaGetSymbolAddress((void**)&g_x2_p,   g_x2);
    float* g_den1_p; cudaGetSymbolAddress((void**)&g_den1_p, g_den1);
    float* g_den2_p; cudaGetSymbolAddress((void**)&g_den2_p, g_den2);

    const int T = 256;
    dim3 gemm_grid(F_H / 128, (Nn + 127) / 128);
    int nh_blocks = (Nn * NHEAD + T - 1) / T;
    int eh_blocks = ((size_t)E * NHEAD + T - 1) / T;
    int nf_blocks = (Nn * F_H + T - 1) / T;
    int fin_blocks = (Nn * 32 + T - 1) / T;

    k_init<<<1024, T>>>();

    // ---------- layer 1 ----------
    k_gemm<F_IN><<<gemm_grid, T>>>(x, W1, g_h_p);
    k_alpha<<<nh_blocks, T>>>(a1s, a1d);
    k_edge<<<eh_blocks, T>>>(ei, E, g_den1_p);
    k_elu1<<<nf_blocks, T>>>(b1);

    // ---------- layer 2 ----------
    k_gemm<F_H><<<gemm_grid, T>>>(g_x2_p, W2, g_h_p);
    k_alpha<<<nh_blocks, T>>>(a2s, a2d);
    k_edge<<<eh_blocks, T>>>(ei, E, g_den2_p);
    k_final<<<fin_blocks, T>>>(b2, Wl, bl, out);
}

// round 3
// speedup vs baseline: 2.7160x; 1.3203x over previous
#include <cuda_runtime.h>
#include <cstdint>

// ---------------- problem constants ----------------
#define Nn     30000
#define F_IN   128
#define F_H    256
#define NHEAD  8
#define CCH    32
#define NEG_SLOPE 0.2f

// ---------------- device scratch (no allocs allowed) ----------------
__device__ float g_h   [(size_t)Nn * F_H];
__device__ float g_agg [(size_t)Nn * F_H];
__device__ float g_x2  [(size_t)Nn * F_H];
__device__ float g_as  [(size_t)Nn * NHEAD];
__device__ float g_ad  [(size_t)Nn * NHEAD];
__device__ float g_den1[(size_t)Nn * NHEAD];
__device__ float g_den2[(size_t)Nn * NHEAD];

__device__ __forceinline__ void red4(float* p, float a, float b, float c, float d) {
    asm volatile("red.global.add.v4.f32 [%0], {%1,%2,%3,%4};"
                 :: "l"(p), "f"(a), "f"(b), "f"(c), "f"(d) : "memory");
}
__device__ __forceinline__ float leaky(float v) {
    return (v > 0.f) ? v : NEG_SLOPE * v;
}
__device__ __forceinline__ unsigned f2tf32(float f) {
    unsigned u;
    asm("cvt.rna.tf32.f32 %0, %1;" : "=r"(u) : "f"(f));
    return u;
}
__device__ __forceinline__ void mma_tf32(float c[4], const unsigned a[4], const unsigned b[2]) {
    asm volatile(
        "mma.sync.aligned.m16n8k8.row.col.f32.tf32.tf32.f32 "
        "{%0,%1,%2,%3}, {%4,%5,%6,%7}, {%8,%9}, {%0,%1,%2,%3};"
        : "+f"(c[0]), "+f"(c[1]), "+f"(c[2]), "+f"(c[3])
        : "r"(a[0]), "r"(a[1]), "r"(a[2]), "r"(a[3]), "r"(b[0]), "r"(b[1]));
}

// ---------------- tf32 MMA GEMM: C[Nn,256] = A[Nn,K] @ W[K,256] ----------------
// Block tile 128x128, BK=16, 256 threads (8 warps), warp tile 32x64.
#define AP 20    // As row pitch (floats): conflict-free, 80B rows (16B aligned)
#define BP 136   // Bs row pitch (floats): conflict-free, 544B rows (16B aligned)

template <int K>
__global__ void __launch_bounds__(256) k_gemm_tf32(const float* __restrict__ A,
                                                   const float* __restrict__ W,
                                                   float* __restrict__ Cout) {
    __shared__ unsigned As[128 * AP];   // [row][k], tf32-encoded
    __shared__ unsigned Bs[16 * BP];    // [k][n],  tf32-encoded

    const int tid    = threadIdx.x;
    const int lane   = tid & 31;
    const int warpid = tid >> 5;
    const int row0   = blockIdx.y * 128;
    const int col0   = blockIdx.x * 128;
    const int wm     = (warpid & 3) * 32;   // warp row offset in tile
    const int wn     = (warpid >> 2) * 64;  // warp col offset in tile
    const int lg     = lane >> 2;           // group id 0..7
    const int lt     = lane & 3;            // thread-in-group 0..3

    float c[2][8][4];
#pragma unroll
    for (int t = 0; t < 2; t++)
#pragma unroll
        for (int j = 0; j < 8; j++)
#pragma unroll
            for (int r = 0; r < 4; r++) c[t][j][r] = 0.f;

    // staging indices
    const int a_row = tid >> 1;                 // 0..127
    const int a_c0  = (tid & 1) * 8;            // 0 or 8 (two float4s each)
    const int b_k   = tid >> 4;                 // 0..15
    const int b_n0  = (tid & 15) * 4;           // 0..60 (then +64)

    for (int k0 = 0; k0 < K; k0 += 16) {
        // ---- stage A [128 x 16] ----
#pragma unroll
        for (int i = 0; i < 2; i++) {
            int col = a_c0 + i * 4;
            float4 v = make_float4(0.f, 0.f, 0.f, 0.f);
            if (row0 + a_row < Nn)
                v = *(const float4*)(A + (size_t)(row0 + a_row) * K + k0 + col);
            uint4 u = make_uint4(f2tf32(v.x), f2tf32(v.y), f2tf32(v.z), f2tf32(v.w));
            *(uint4*)&As[a_row * AP + col] = u;
        }
        // ---- stage B [16 x 128] ----
#pragma unroll
        for (int i = 0; i < 2; i++) {
            int n = b_n0 + i * 64;
            float4 v = *(const float4*)(W + (size_t)(k0 + b_k) * F_H + col0 + n);
            uint4 u = make_uint4(f2tf32(v.x), f2tf32(v.y), f2tf32(v.z), f2tf32(v.w));
            *(uint4*)&Bs[b_k * BP + n] = u;
        }
        __syncthreads();

#pragma unroll
        for (int kk = 0; kk < 16; kk += 8) {
            unsigned a[2][4];
#pragma unroll
            for (int t = 0; t < 2; t++) {
                int mr = wm + t * 16;
                a[t][0] = As[(mr + lg) * AP + kk + lt];
                a[t][1] = As[(mr + lg + 8) * AP + kk + lt];
                a[t][2] = As[(mr + lg) * AP + kk + lt + 4];
                a[t][3] = As[(mr + lg + 8) * AP + kk + lt + 4];
            }
#pragma unroll
            for (int j = 0; j < 8; j++) {
                unsigned b[2];
                int n = wn + j * 8 + lg;
                b[0] = Bs[(kk + lt) * BP + n];
                b[1] = Bs[(kk + lt + 4) * BP + n];
                mma_tf32(c[0][j], a[0], b);
                mma_tf32(c[1][j], a[1], b);
            }
        }
        __syncthreads();
    }

    // ---- store ----
#pragma unroll
    for (int t = 0; t < 2; t++) {
        int r0 = row0 + wm + t * 16 + lg;
#pragma unroll
        for (int j = 0; j < 8; j++) {
            int cc = col0 + wn + j * 8 + lt * 2;
            if (r0 < Nn)
                *(float2*)(Cout + (size_t)r0 * F_H + cc) = make_float2(c[t][j][0], c[t][j][1]);
            if (r0 + 8 < Nn)
                *(float2*)(Cout + (size_t)(r0 + 8) * F_H + cc) = make_float2(c[t][j][2], c[t][j][3]);
        }
    }
}

// ---------------- alpha projections ----------------
__global__ void k_alpha(const float* __restrict__ a_src, const float* __restrict__ a_dst) {
    int idx = blockIdx.x * blockDim.x + threadIdx.x;
    if (idx >= Nn * NHEAD) return;
    int n = idx >> 3, h = idx & 7;
    const float4* hp = (const float4*)(g_h + (size_t)n * F_H + h * CCH);
    const float4* as = (const float4*)(a_src + h * CCH);
    const float4* ad = (const float4*)(a_dst + h * CCH);
    float s = 0.f, d = 0.f;
#pragma unroll
    for (int i = 0; i < 8; i++) {
        float4 v = hp[i], a = as[i], b = ad[i];
        s += v.x * a.x + v.y * a.y + v.z * a.z + v.w * a.w;
        d += v.x * b.x + v.y * b.y + v.z * b.z + v.w * b.w;
    }
    g_as[idx] = s;
    g_ad[idx] = d;
}

// ---------------- init accumulators ----------------
__global__ void k_init() {
    for (int i = blockIdx.x * blockDim.x + threadIdx.x; i < Nn * F_H;
         i += gridDim.x * blockDim.x) {
        g_agg[i] = 0.f;
        if (i < Nn * NHEAD) { g_den1[i] = 0.f; g_den2[i] = 0.f; }
    }
}

// ---------------- fused edge pass ----------------
// 8 lanes per edge; lane j computes head-j weight, shuffles for the rest.
__global__ void k_edge(const int* __restrict__ ei, int E, float* __restrict__ den) {
    int idx = blockIdx.x * blockDim.x + threadIdx.x;
    bool valid = idx < E * NHEAD;
    unsigned mask = __ballot_sync(0xFFFFFFFFu, valid);
    if (!valid) return;
    int e = idx >> 3, j = idx & 7;
    int src = __ldg(&ei[e]);
    int dst = __ldg(&ei[E + e]);

    float wj = __expf(leaky(g_as[src * NHEAD + j] + g_ad[dst * NHEAD + j]));
    atomicAdd(&den[dst * NHEAD + j], wj);

    float w[8];
#pragma unroll
    for (int i = 0; i < 8; i++) w[i] = __shfl_sync(mask, wj, i, 8);

    const float* hp = g_h + (size_t)src * F_H + j * 4;
    float* op = g_agg + (size_t)dst * F_H + j * 4;
#pragma unroll
    for (int i = 0; i < 8; i++) {        // per-head float4; 128B-contiguous per warp-instr
        float4 v = *(const float4*)(hp + i * 32);
        red4(op + i * 32, v.x * w[i], v.y * w[i], v.z * w[i], v.w * w[i]);
    }
}

// ---------------- epilogue layer 1 (folds self-loop; re-zeros g_agg) ----------------
__global__ void k_elu1(const float* __restrict__ b) {
    int idx = blockIdx.x * blockDim.x + threadIdx.x;
    if (idx >= Nn * F_H) return;
    int n = idx >> 8, f = idx & 255, h = f >> 5;
    float ws = __expf(leaky(g_as[n * NHEAD + h] + g_ad[n * NHEAD + h]));
    float num = g_agg[idx] + ws * g_h[idx];
    float den = g_den1[n * NHEAD + h] + ws;
    float v = num / den + b[f];
    g_x2[idx] = (v > 0.f) ? v : expm1f(v);
    g_agg[idx] = 0.f;
}

// ---------------- epilogue layer 2 + linear head ----------------
__global__ void k_final(const float* __restrict__ b2, const float* __restrict__ Wl,
                        const float* __restrict__ bl, float* __restrict__ out) {
    int gid = blockIdx.x * blockDim.x + threadIdx.x;
    int n = gid >> 5, lane = gid & 31;
    if (n >= Nn) return;
    float s = 0.f;
#pragma unroll
    for (int k = 0; k < 8; k++) {
        int f = lane + 32 * k;
        float ws = __expf(leaky(g_as[n * NHEAD + k] + g_ad[n * NHEAD + k]));
        float num = g_agg[(size_t)n * F_H + f] + ws * g_h[(size_t)n * F_H + f];
        float den = g_den2[n * NHEAD + k] + ws;
        float v = num / den + b2[f];
        v = (v > 0.f) ? v : expm1f(v);
        s += v * Wl[f];
    }
#pragma unroll
    for (int o = 16; o > 0; o >>= 1) s += __shfl_down_sync(0xFFFFFFFFu, s, o);
    if (lane == 0) out[n] = s + bl[0];
}

// ---------------- host ----------------
extern "C" void kernel_launch(void* const* d_in, const int* in_sizes, int n_in,
                              void* d_out, int out_size) {
    const float* x   = (const float*)d_in[0];
    const int*   ei  = (const int*)  d_in[1];
    const float* W1  = (const float*)d_in[2];
    const float* a1s = (const float*)d_in[3];
    const float* a1d = (const float*)d_in[4];
    const float* b1  = (const float*)d_in[5];
    const float* W2  = (const float*)d_in[6];
    const float* a2s = (const float*)d_in[7];
    const float* a2d = (const float*)d_in[8];
    const float* b2  = (const float*)d_in[9];
    const float* Wl  = (const float*)d_in[10];
    const float* bl  = (const float*)d_in[11];
    float* out = (float*)d_out;

    const int E = in_sizes[1] / 2;          // 480000

    float* g_h_p;    cudaGetSymbolAddress((void**)&g_h_p,    g_h);
    float* g_x2_p;   cudaGetSymbolAddress((void**)&g_x2_p,   g_x2);
    float* g_den1_p; cudaGetSymbolAddress((void**)&g_den1_p, g_den1);
    float* g_den2_p; cudaGetSymbolAddress((void**)&g_den2_p, g_den2);

    const int T = 256;
    dim3 gemm_grid(F_H / 128, (Nn + 127) / 128);
    int nh_blocks  = (Nn * NHEAD + T - 1) / T;
    int eh_blocks  = ((size_t)E * NHEAD + T - 1) / T;
    int nf_blocks  = (Nn * F_H + T - 1) / T;
    int fin_blocks = (Nn * 32 + T - 1) / T;

    k_init<<<1024, T>>>();

    // ---------- layer 1 ----------
    k_gemm_tf32<F_IN><<<gemm_grid, T>>>(x, W1, g_h_p);
    k_alpha<<<nh_blocks, T>>>(a1s, a1d);
    k_edge<<<eh_blocks, T>>>(ei, E, g_den1_p);
    k_elu1<<<nf_blocks, T>>>(b1);

    // ---------- layer 2 ----------
    k_gemm_tf32<F_H><<<gemm_grid, T>>>(g_x2_p, W2, g_h_p);
    k_alpha<<<nh_blocks, T>>>(a2s, a2d);
    k_edge<<<eh_blocks, T>>>(ei, E, g_den2_p);
    k_final<<<fin_blocks, T>>>(b2, Wl, bl, out);
}